// round 3
// baseline (speedup 1.0000x reference)
#include <cuda_runtime.h>

#define N_    2
#define CIN   32
#define T_    8
#define H_    56
#define W_    56
#define COUT  64
#define KVOL  27
#define SP    25088   // T*H*W
#define HW    3136    // H*W
#define RS    132     // padded row stride (floats) for col/w smem rows (16 rows = c-pairs)
#define TAPW  (16*RS) // 2112 floats per tap slice

typedef unsigned long long u64;

// Scratch (no allocations allowed in kernel_launch)
__device__ float g_xt[(size_t)N_ * SP * CIN];   // x -> [N, T*H*W, C]
__device__ float g_wt[KVOL * TAPW];             // weights -> [k][cp][co*2 + (c&1)], padded rows

__device__ __forceinline__ u64 ffma2(u64 a, u64 b, u64 c) {
    u64 d;
    asm("fma.rn.f32x2 %0, %1, %2, %3;" : "=l"(d) : "l"(a), "l"(b), "l"(c));
    return d;
}
__device__ __forceinline__ void unpack2(u64 v, float& lo, float& hi) {
    asm("mov.b64 {%0, %1}, %2;" : "=f"(lo), "=f"(hi) : "l"(v));
}

// ---------------------------------------------------------------------------
// x: [N, C, T*H*W] -> g_xt: [N, T*H*W, C]
// ---------------------------------------------------------------------------
__global__ __launch_bounds__(256) void transpose_x(const float* __restrict__ x) {
    __shared__ float sm[32][33];
    int n  = blockIdx.y;
    int s0 = blockIdx.x * 32;
    int tx = threadIdx.x & 31;
    int ty = threadIdx.x >> 5;
#pragma unroll
    for (int r = 0; r < 4; ++r) {
        int c = ty + r * 8;
        sm[c][tx] = x[((size_t)n * CIN + c) * SP + s0 + tx];
    }
    __syncthreads();
#pragma unroll
    for (int r = 0; r < 4; ++r) {
        int j = ty + r * 8;
        g_xt[((size_t)n * SP + s0 + j) * CIN + tx] = sm[tx][j];
    }
}

// weight: [co, c, k] -> g_wt: [k][(c>>1)*RS + co*2 + (c&1)]
__global__ void transpose_w(const float* __restrict__ w) {
    int i = blockIdx.x * blockDim.x + threadIdx.x;
    if (i >= KVOL * CIN * COUT) return;
    int k  = i >> 11;          // / 2048
    int r  = i & 2047;
    int c  = r >> 6;
    int co = r & 63;
    g_wt[k * TAPW + (c >> 1) * RS + co * 2 + (c & 1)] =
        w[((size_t)co * CIN + c) * KVOL + k];
}

// ---------------------------------------------------------------------------
// offsets for this warp's 8 positions, lane-parallel (lane&7 = position)
// ---------------------------------------------------------------------------
__device__ __forceinline__ float3 load_off(const float* __restrict__ offset,
                                           int n, int k, int sbase, int lane) {
    size_t b = ((size_t)n * 81 + k * 3) * SP + sbase + (lane & 7);
    float3 o;
    o.x = offset[b];
    o.y = offset[b + SP];
    o.z = offset[b + 2 * (size_t)SP];
    return o;
}

// ---------------------------------------------------------------------------
// Gather one tap into col buffer (pair-over-c layout) + stage its weight slice
// ---------------------------------------------------------------------------
__device__ __forceinline__ void gather_and_stage(
    int k, float3 of, const float* __restrict__ xb,
    const float* btc, const float* bhc, const float* bwc,
    int lane, int warpId, int tid, float* colb, float* wb)
{
    // stage weight slice (already in final layout in g_wt)
    {
        const float4* wg = (const float4*)(g_wt + k * TAPW);
        float4* ws = (float4*)wb;
        ws[tid]       = wg[tid];
        ws[tid + 256] = wg[tid + 256];
        if (tid < 16) ws[tid + 512] = wg[tid + 512];
    }

    int kt = k / 9;
    int r9 = k - kt * 9;
    int kh = r9 / 3;
    int kw = r9 - kh * 3;
    float ktf = (float)kt, khf = (float)kh, kwf = (float)kw;

#pragma unroll
    for (int pp = 0; pp < 8; ++pp) {
        int q = warpId * 8 + pp;
        float pt = btc[pp] + ktf + __shfl_sync(0xffffffffu, of.x, pp);
        float ph = bhc[pp] + khf + __shfl_sync(0xffffffffu, of.y, pp);
        float pw = bwc[pp] + kwf + __shfl_sync(0xffffffffu, of.z, pp);

        float tf = floorf(pt), hf = floorf(ph), wf = floorf(pw);
        int t0 = (int)tf, h0 = (int)hf, w0 = (int)wf;
        float lt = pt - tf, lh = ph - hf, lw = pw - wf;

        float val;
        if (t0 >= 0 && t0 <= T_ - 2 && h0 >= 0 && h0 <= H_ - 2 &&
            w0 >= 0 && w0 <= W_ - 2) {
            const float* p = xb + ((size_t)((t0 * H_ + h0) * W_ + w0) << 5) + lane;
            float v000 = p[0],        v001 = p[32];
            float v010 = p[W_ * 32],  v011 = p[W_ * 32 + 32];
            const float* p1 = p + HW * 32;
            float v100 = p1[0],       v101 = p1[32];
            float v110 = p1[W_ * 32], v111 = p1[W_ * 32 + 32];
            float c00 = v000 + lw * (v001 - v000);
            float c01 = v010 + lw * (v011 - v010);
            float c10 = v100 + lw * (v101 - v100);
            float c11 = v110 + lw * (v111 - v110);
            float c0 = c00 + lh * (c01 - c00);
            float c1 = c10 + lh * (c11 - c10);
            val = c0 + lt * (c1 - c0);
        } else {
            val = 0.f;
#pragma unroll
            for (int ct = 0; ct < 2; ++ct) {
                int ti = t0 + ct;
                float wt = ct ? lt : 1.f - lt;
                if (ti < 0 || ti >= T_) continue;
#pragma unroll
                for (int ch = 0; ch < 2; ++ch) {
                    int hi = h0 + ch;
                    float wh = ch ? lh : 1.f - lh;
                    if (hi < 0 || hi >= H_) continue;
#pragma unroll
                    for (int cw = 0; cw < 2; ++cw) {
                        int wi = w0 + cw;
                        float ww = cw ? lw : 1.f - lw;
                        if (wi < 0 || wi >= W_) continue;
                        val += wt * wh * ww *
                               xb[((size_t)((ti * H_ + hi) * W_ + wi) << 5) + lane];
                    }
                }
            }
        }
        // pair-over-c layout: [cp][q*2 + (c&1)]
        colb[(lane >> 1) * RS + q * 2 + (lane & 1)] = val;
    }
}

// ---------------------------------------------------------------------------
// Main kernel: block = 64 positions x 64 couts, 256 threads, double-buffered.
// ---------------------------------------------------------------------------
__global__ __launch_bounds__(256, 2) void deform_conv3d_main(
    const float* __restrict__ offset,
    const float* __restrict__ bias,
    float* __restrict__ out)
{
    __shared__ __align__(16) float col[2][TAPW];
    __shared__ __align__(16) float wsm[2][TAPW];

    const int n   = blockIdx.y;
    const int s0  = blockIdx.x * 64;
    const int tid = threadIdx.x;
    const int lane   = tid & 31;
    const int warpId = tid >> 5;
    const int cg = tid & 15;     // cout group (4 couts)
    const int pg = tid >> 4;     // pos group (4 positions)
    const int sbase = s0 + warpId * 8;

    // base sampling coords for this warp's 8 positions
    float btc[8], bhc[8], bwc[8];
#pragma unroll
    for (int pp = 0; pp < 8; ++pp) {
        int s  = sbase + pp;
        int to = s / HW;
        int rem = s - to * HW;
        int ho = rem / W_;
        int wo = rem - ho * W_;
        btc[pp] = (float)(to - 1);
        bhc[pp] = (float)(ho - 1);
        bwc[pp] = (float)(wo - 1);
    }

    u64 acc[16];   // acc[i*4+j] = (co 4cg+i, pos 4pg+j), even/odd-c partials
#pragma unroll
    for (int i = 0; i < 16; ++i) acc[i] = 0ull;

    const float* __restrict__ xb = g_xt + (size_t)n * SP * CIN;

    // prologue: gather tap 0, prefetch offsets for tap 1
    float3 ofA = load_off(offset, n, 0, sbase, lane);
    float3 ofN = load_off(offset, n, 1, sbase, lane);
    gather_and_stage(0, ofA, xb, btc, bhc, bwc, lane, warpId, tid,
                     col[0], wsm[0]);
    ofA = ofN;
    __syncthreads();

    for (int k = 0; k < KVOL; ++k) {
        const int cur = k & 1;
        const int nxt = cur ^ 1;

        float3 ofB = ofA;
        if (k + 2 < KVOL) ofB = load_off(offset, n, k + 2, sbase, lane);
        if (k + 1 < KVOL)
            gather_and_stage(k + 1, ofA, xb, btc, bhc, bwc, lane, warpId, tid,
                             col[nxt], wsm[nxt]);

        // phase 2: rank-32 update, pair-over-c, no packs, no duplication
        const float* cb = col[cur];
        const float* wb = wsm[cur];
#pragma unroll
        for (int cp = 0; cp < 16; ++cp) {
            const float* wr = wb + cp * RS + (cg << 3);
            const float* cr = cb + cp * RS + (pg << 3);
            ulonglong2 wA = *(const ulonglong2*)wr;        // co 4cg, 4cg+1
            ulonglong2 wB = *(const ulonglong2*)(wr + 4);  // co 4cg+2, 4cg+3
            ulonglong2 vA = *(const ulonglong2*)cr;        // pos 4pg, 4pg+1
            ulonglong2 vB = *(const ulonglong2*)(cr + 4);  // pos 4pg+2, 4pg+3
            acc[0]  = ffma2(wA.x, vA.x, acc[0]);
            acc[1]  = ffma2(wA.x, vA.y, acc[1]);
            acc[2]  = ffma2(wA.x, vB.x, acc[2]);
            acc[3]  = ffma2(wA.x, vB.y, acc[3]);
            acc[4]  = ffma2(wA.y, vA.x, acc[4]);
            acc[5]  = ffma2(wA.y, vA.y, acc[5]);
            acc[6]  = ffma2(wA.y, vB.x, acc[6]);
            acc[7]  = ffma2(wA.y, vB.y, acc[7]);
            acc[8]  = ffma2(wB.x, vA.x, acc[8]);
            acc[9]  = ffma2(wB.x, vA.y, acc[9]);
            acc[10] = ffma2(wB.x, vB.x, acc[10]);
            acc[11] = ffma2(wB.x, vB.y, acc[11]);
            acc[12] = ffma2(wB.y, vA.x, acc[12]);
            acc[13] = ffma2(wB.y, vA.y, acc[13]);
            acc[14] = ffma2(wB.y, vB.x, acc[14]);
            acc[15] = ffma2(wB.y, vB.y, acc[15]);
        }

        ofA = ofB;
        __syncthreads();
    }

    // epilogue: fold even/odd-c partials, add bias, vectorized stores
    float4 b4 = *(const float4*)(bias + (cg << 2));
    float bb[4] = {b4.x, b4.y, b4.z, b4.w};
#pragma unroll
    for (int i = 0; i < 4; ++i) {
        float r[4];
#pragma unroll
        for (int j = 0; j < 4; ++j) {
            float lo, hi;
            unpack2(acc[i * 4 + j], lo, hi);
            r[j] = lo + hi + bb[i];
        }
        float4 o = {r[0], r[1], r[2], r[3]};
        *(float4*)(out + ((size_t)n * COUT + (cg << 2) + i) * SP + s0 + (pg << 2)) = o;
    }
}

// ---------------------------------------------------------------------------
extern "C" void kernel_launch(void* const* d_in, const int* in_sizes, int n_in,
                              void* d_out, int out_size) {
    const float* x      = (const float*)d_in[0];
    const float* offset = (const float*)d_in[1];
    const float* weight = (const float*)d_in[2];
    const float* bias   = (const float*)d_in[3];
    float* out = (float*)d_out;

    dim3 gT(SP / 32, N_);
    transpose_x<<<gT, 256>>>(x);
    transpose_w<<<(KVOL * CIN * COUT + 255) / 256, 256>>>(weight);

    dim3 gM(SP / 64, N_);
    deform_conv3d_main<<<gM, 256>>>(offset, bias, out);
}

// round 4
// speedup vs baseline: 1.1698x; 1.1698x over previous
#include <cuda_runtime.h>

#define N_    2
#define CIN   32
#define T_    8
#define H_    56
#define W_    56
#define COUT  64
#define KVOL  27
#define SP    25088   // T*H*W
#define HW    3136    // H*W
#define CRS   132     // col row stride (floats), 16B-aligned, conflict-friendly
#define WRS   128     // weight row stride (floats)

typedef unsigned long long u64;

// Scratch (no allocations allowed in kernel_launch)
__device__ float g_xt[(size_t)N_ * SP * CIN];   // x -> [N, T*H*W, C]
__device__ float g_wt[KVOL * 16 * WRS];         // w -> [k][cp][co*2 + (c&1)]

// ---- packed f32x2 helpers ---------------------------------------------------
__device__ __forceinline__ u64 ffma2(u64 a, u64 b, u64 c) {
    u64 d; asm("fma.rn.f32x2 %0, %1, %2, %3;" : "=l"(d) : "l"(a), "l"(b), "l"(c));
    return d;
}
__device__ __forceinline__ u64 fmul2(u64 a, u64 b) {
    u64 d; asm("mul.rn.f32x2 %0, %1, %2;" : "=l"(d) : "l"(a), "l"(b));
    return d;
}
__device__ __forceinline__ u64 pack2(float x) {
    u64 d; asm("mov.b64 %0, {%1, %2};" : "=l"(d) : "f"(x), "f"(x));
    return d;
}
__device__ __forceinline__ void unpack2(u64 v, float& lo, float& hi) {
    asm("mov.b64 {%0, %1}, %2;" : "=f"(lo), "=f"(hi) : "l"(v));
}

// ---------------------------------------------------------------------------
// x: [N, C, T*H*W] -> g_xt: [N, T*H*W, C]
// ---------------------------------------------------------------------------
__global__ __launch_bounds__(256) void transpose_x(const float* __restrict__ x) {
    __shared__ float sm[32][33];
    int n  = blockIdx.y;
    int s0 = blockIdx.x * 32;
    int tx = threadIdx.x & 31;
    int ty = threadIdx.x >> 5;
#pragma unroll
    for (int r = 0; r < 4; ++r) {
        int c = ty + r * 8;
        sm[c][tx] = x[((size_t)n * CIN + c) * SP + s0 + tx];
    }
    __syncthreads();
#pragma unroll
    for (int r = 0; r < 4; ++r) {
        int j = ty + r * 8;
        g_xt[((size_t)n * SP + s0 + j) * CIN + tx] = sm[tx][j];
    }
}

// weight: [co, c, k] -> g_wt: [k][(c>>1)*WRS + co*2 + (c&1)]
__global__ void transpose_w(const float* __restrict__ w) {
    int i = blockIdx.x * blockDim.x + threadIdx.x;
    if (i >= KVOL * CIN * COUT) return;
    int k  = i >> 11;
    int r  = i & 2047;
    int c  = r >> 6;
    int co = r & 63;
    g_wt[k * (16 * WRS) + (c >> 1) * WRS + co * 2 + (c & 1)] =
        w[((size_t)co * CIN + c) * KVOL + k];
}

// ---------------------------------------------------------------------------
// Main kernel: block = 64 positions x 64 couts, 256 threads.
// col:  [cp(16)][q*2 + c-parity]   (u64 per (cp,q) = even/odd-c pair)
// wsm:  [cp(16)][co*2 + c-parity]
// phase 2: thread = (cout-pair cg=tid&31, warpId=pos octet); acc u64 holds e/o-c partials.
// ---------------------------------------------------------------------------
__global__ __launch_bounds__(256) void deform_conv3d_main(
    const float* __restrict__ offset,
    const float* __restrict__ bias,
    float* __restrict__ out)
{
    __shared__ __align__(16) float col[16 * CRS];
    __shared__ __align__(16) float wsm[16 * WRS];
    __shared__ float osm[81 * 64];

    const int n   = blockIdx.y;
    const int s0  = blockIdx.x * 64;
    const int tid = threadIdx.x;
    const int lane   = tid & 31;
    const int warpId = tid >> 5;
    const int cp = lane & 15;        // phase 1: channel pair (c = 2cp, 2cp+1)
    const int qh = lane >> 4;        // phase 1: position half (0/1)
    const int cg = tid & 31;         // phase 2: cout pair (co = 2cg, 2cg+1)

    // stage offsets for the block (coalesced, once)
    for (int i = tid; i < 81 * 64; i += 256) {
        int ch = i >> 6, j = i & 63;
        osm[i] = offset[((size_t)n * 81 + ch) * SP + s0 + j];
    }

    // base coords for this lane's 4 positions (q = warpId*8 + it*2 + qh)
    float btc[4], bhc[4], bwc[4];
#pragma unroll
    for (int it = 0; it < 4; ++it) {
        int s  = s0 + warpId * 8 + it * 2 + qh;
        int to = s / HW;
        int rem = s - to * HW;
        int ho = rem / W_;
        int wo = rem - ho * W_;
        btc[it] = (float)(to - 1);
        bhc[it] = (float)(ho - 1);
        bwc[it] = (float)(wo - 1);
    }

    u64 acc[2][8];   // [cout in pair][pos 0..7], halves = even/odd-c partials
#pragma unroll
    for (int i = 0; i < 2; ++i)
#pragma unroll
        for (int j = 0; j < 8; ++j) acc[i][j] = 0ull;

    const float* __restrict__ xb = g_xt + (size_t)n * SP * CIN;
    __syncthreads();   // osm ready

    for (int k = 0; k < KVOL; ++k) {
        // ---- stage weight slice (already in final layout) ----
        {
            const float4* wg = (const float4*)(g_wt + k * (16 * WRS));
            float4* ws = (float4*)wsm;
            ws[tid]       = wg[tid];
            ws[tid + 256] = wg[tid + 256];
        }

        int kt = k / 9;
        int r9 = k - kt * 9;
        int kh = r9 / 3;
        int kw = r9 - kh * 3;
        float ktf = (float)kt, khf = (float)kh, kwf = (float)kw;
        const float* o0 = osm + (k * 3 + 0) * 64;
        const float* o1 = osm + (k * 3 + 1) * 64;
        const float* o2 = osm + (k * 3 + 2) * 64;

        // ---- phase 1: packed trilinear gather (2 channels per lane) ----
#pragma unroll
        for (int it = 0; it < 4; ++it) {
            int q = warpId * 8 + it * 2 + qh;
            float pt = btc[it] + ktf + o0[q];
            float ph = bhc[it] + khf + o1[q];
            float pw = bwc[it] + kwf + o2[q];
            float tf = floorf(pt), hf = floorf(ph), wf = floorf(pw);
            int t0 = (int)tf, h0 = (int)hf, w0 = (int)wf;
            float lt = pt - tf, lh = ph - hf, lw = pw - wf;

            u64 val2;
            if (t0 >= 0 && t0 <= T_ - 2 && h0 >= 0 && h0 <= H_ - 2 &&
                w0 >= 0 && w0 <= W_ - 2) {
                const u64* p = (const u64*)(xb +
                    ((size_t)((t0 * H_ + h0) * W_ + w0) << 5) + 2 * cp);
                u64 v000 = p[0],       v001 = p[16];
                u64 v010 = p[W_ * 16], v011 = p[W_ * 16 + 16];
                const u64* p1 = p + HW * 16;
                u64 v100 = p1[0],       v101 = p1[16];
                u64 v110 = p1[W_ * 16], v111 = p1[W_ * 16 + 16];
                u64 w0p = pack2(1.f - lw), w1p = pack2(lw);
                u64 h0p = pack2(1.f - lh), h1p = pack2(lh);
                u64 t0p = pack2(1.f - lt), t1p = pack2(lt);
                u64 c00 = ffma2(v001, w1p, fmul2(v000, w0p));
                u64 c01 = ffma2(v011, w1p, fmul2(v010, w0p));
                u64 c10 = ffma2(v101, w1p, fmul2(v100, w0p));
                u64 c11 = ffma2(v111, w1p, fmul2(v110, w0p));
                u64 c0  = ffma2(c01, h1p, fmul2(c00, h0p));
                u64 c1  = ffma2(c11, h1p, fmul2(c10, h0p));
                val2    = ffma2(c1, t1p, fmul2(c0, t0p));
            } else {
                val2 = 0ull;
#pragma unroll
                for (int ct = 0; ct < 2; ++ct) {
                    int ti = t0 + ct;
                    float wt = ct ? lt : 1.f - lt;
                    if (ti < 0 || ti >= T_) continue;
#pragma unroll
                    for (int ch = 0; ch < 2; ++ch) {
                        int hi = h0 + ch;
                        float wh = ch ? lh : 1.f - lh;
                        if (hi < 0 || hi >= H_) continue;
#pragma unroll
                        for (int cw = 0; cw < 2; ++cw) {
                            int wi = w0 + cw;
                            float ww = cw ? lw : 1.f - lw;
                            if (wi < 0 || wi >= W_) continue;
                            u64 v = *(const u64*)(xb +
                                ((size_t)((ti * H_ + hi) * W_ + wi) << 5) + 2 * cp);
                            val2 = ffma2(v, pack2(wt * wh * ww), val2);
                        }
                    }
                }
            }
            *(u64*)(col + cp * CRS + q * 2) = val2;
        }
        __syncthreads();

        // ---- phase 2: rank-32 update (2 couts x 8 pos, even/odd-c packed) ----
        {
            const int qb = warpId * 8;
#pragma unroll
            for (int c2 = 0; c2 < 16; ++c2) {
                ulonglong2 w2 = *(const ulonglong2*)(wsm + c2 * WRS + (cg << 2));
                const float* cr = col + c2 * CRS + qb * 2;
                ulonglong2 vA = *(const ulonglong2*)(cr);       // pos qb, qb+1
                ulonglong2 vB = *(const ulonglong2*)(cr + 4);   // pos qb+2, qb+3
                ulonglong2 vC = *(const ulonglong2*)(cr + 8);   // pos qb+4, qb+5
                ulonglong2 vD = *(const ulonglong2*)(cr + 12);  // pos qb+6, qb+7
                acc[0][0] = ffma2(w2.x, vA.x, acc[0][0]);
                acc[0][1] = ffma2(w2.x, vA.y, acc[0][1]);
                acc[0][2] = ffma2(w2.x, vB.x, acc[0][2]);
                acc[0][3] = ffma2(w2.x, vB.y, acc[0][3]);
                acc[0][4] = ffma2(w2.x, vC.x, acc[0][4]);
                acc[0][5] = ffma2(w2.x, vC.y, acc[0][5]);
                acc[0][6] = ffma2(w2.x, vD.x, acc[0][6]);
                acc[0][7] = ffma2(w2.x, vD.y, acc[0][7]);
                acc[1][0] = ffma2(w2.y, vA.x, acc[1][0]);
                acc[1][1] = ffma2(w2.y, vA.y, acc[1][1]);
                acc[1][2] = ffma2(w2.y, vB.x, acc[1][2]);
                acc[1][3] = ffma2(w2.y, vB.y, acc[1][3]);
                acc[1][4] = ffma2(w2.y, vC.x, acc[1][4]);
                acc[1][5] = ffma2(w2.y, vC.y, acc[1][5]);
                acc[1][6] = ffma2(w2.y, vD.x, acc[1][6]);
                acc[1][7] = ffma2(w2.y, vD.y, acc[1][7]);
            }
        }
        __syncthreads();
    }

    // ---- epilogue: fold even/odd-c halves, add bias, direct float4 stores ----
#pragma unroll
    for (int i = 0; i < 2; ++i) {
        int co = 2 * cg + i;
        float b = bias[co];
        float r[8];
#pragma unroll
        for (int j = 0; j < 8; ++j) {
            float lo, hi;
            unpack2(acc[i][j], lo, hi);
            r[j] = lo + hi + b;
        }
        float* op = out + ((size_t)n * COUT + co) * SP + s0 + warpId * 8;
        *(float4*)(op)     = make_float4(r[0], r[1], r[2], r[3]);
        *(float4*)(op + 4) = make_float4(r[4], r[5], r[6], r[7]);
    }
}

// ---------------------------------------------------------------------------
extern "C" void kernel_launch(void* const* d_in, const int* in_sizes, int n_in,
                              void* d_out, int out_size) {
    const float* x      = (const float*)d_in[0];
    const float* offset = (const float*)d_in[1];
    const float* weight = (const float*)d_in[2];
    const float* bias   = (const float*)d_in[3];
    float* out = (float*)d_out;

    dim3 gT(SP / 32, N_);
    transpose_x<<<gT, 256>>>(x);
    transpose_w<<<(KVOL * CIN * COUT + 255) / 256, 256>>>(weight);

    dim3 gM(SP / 64, N_);
    deform_conv3d_main<<<gM, 256>>>(offset, bias, out);
}